// round 14
// baseline (speedup 1.0000x reference)
#include <cuda_runtime.h>
#include <cuda_bf16.h>
#include <math.h>

#define NUM_LEVELS 16
#define TABLE_SIZE (1u << 19)
#define TSAMP 192
#define PTS 128            // points per block
#define NTHREADS 256
#define FS64 36            // feats row stride, uint2(8B) units: (4r+c)%16 bijective
#define WS64 68            // W row stride, uint2 units: (4c+r)%16 bijective

struct LevelParams {
    float scale[NUM_LEVELS];
    int   res[NUM_LEVELS];
    unsigned hashed_mask;
};

__device__ __forceinline__ float softplus10(float v) {
    float y = 10.0f * v;
    float t = __expf(-fabsf(y));
    return (fmaxf(y, 0.0f) + __logf(1.0f + t)) * 0.1f;
}

__device__ __forceinline__ unsigned pack_bf16x2(float lo_val, float hi_val) {
    unsigned r;
    asm("cvt.rn.bf16x2.f32 %0, %1, %2;" : "=r"(r) : "f"(hi_val), "f"(lo_val));
    return r;
}

#define MMA_BF16(C, A0, A1, A2, A3, B0, B1)                                    \
    asm volatile(                                                              \
        "mma.sync.aligned.m16n8k16.row.col.f32.bf16.bf16.f32 "                 \
        "{%0,%1,%2,%3}, {%4,%5,%6,%7}, {%8,%9}, {%0,%1,%2,%3};"                \
        : "+f"(C[0]), "+f"(C[1]), "+f"(C[2]), "+f"(C[3])                       \
        : "r"(A0), "r"(A1), "r"(A2), "r"(A3), "r"(B0), "r"(B1));

__global__ __launch_bounds__(NTHREADS, 3)
void nerf_fused(const float* __restrict__ x,
                const float4* __restrict__ emb,
                const float* __restrict__ W0,
                const float* __restrict__ b0,
                const float* __restrict__ W1,
                const float* __restrict__ b1,
                float* __restrict__ out,
                LevelParams lp)
{
    extern __shared__ unsigned smu[];
    uint2* FHL = (uint2*)smu;                  // [PTS][FS64]  {hi,lo} bf16x2 feats
    uint2* BHL = FHL + PTS * FS64;             // [32][WS64]   {hi,lo} bf16x2 W0
    float* sb0 = (float*)(BHL + 32 * WS64);    // [64]
    float* sW1 = sb0 + 64;                     // [64]
    float* sbuf = sW1 + 64;                    // [PTS] cross-warp partial sums
    float* sb1 = sbuf + PTS;                   // [1]

    const int tid = threadIdx.x;

    // ---- W0 -> bf16 {hi,lo}, packed over k-pairs, interleaved ----
    for (int e = tid; e < 2048; e += NTHREADS) {
        int k2 = e >> 6, n = e & 63;
        float w0v = W0[(2 * k2) * 64 + n];
        float w1v = W0[(2 * k2 + 1) * 64 + n];
        float h0f = __bfloat162float(__float2bfloat16(w0v));
        float h1f = __bfloat162float(__float2bfloat16(w1v));
        uint2 v;
        v.x = pack_bf16x2(h0f, h1f);
        v.y = pack_bf16x2(w0v - h0f, w1v - h1f);
        BHL[k2 * WS64 + n] = v;
    }
    if (tid < 64) { sb0[tid] = b0[tid]; sW1[tid] = W1[tid]; }
    if (tid == 0) { sb1[0] = b1[0]; }

    // ---- Phase 1: gather; 2 threads/point, interleaved levels ----
    const int pt   = tid & (PTS - 1);
    const int half = tid >> 7;
    const int p    = blockIdx.x * PTS + pt;
    const int ray  = p / TSAMP;
    const int t    = p - ray * TSAMP;

    const float2* xr = (const float2*)(x + (size_t)ray * (TSAMP * 2));
    float2 o  = xr[0];
    float2 en = xr[TSAMP - 1];
    float dxr = en.x - o.x, dyr = en.y - o.y;
    float nrm = sqrtf(dxr * dxr + dyr * dyr);
    dxr /= nrm; dyr /= nrm;

    const float step = 2.0f / 191.0f;
    float z  = step * (float)t;
    float ux = (fminf(fmaxf(o.x + dxr * z, -1.0f), 1.0f) + 1.0f) * 0.5f;
    float uy = (fminf(fmaxf(o.y + dyr * z, -1.0f), 1.0f) + 1.0f) * 0.5f;

    uint2* f_row = FHL + pt * FS64;
    #pragma unroll
    for (int l2 = 0; l2 < 8; ++l2) {
        int l = 2 * l2 + half;                  // interleaved level assignment
        float s = lp.scale[l];
        float posx = ux * s + 0.5f;
        float posy = uy * s + 0.5f;
        float pfx = floorf(posx), pfy = floorf(posy);
        float frx = posx - pfx,   fry = posy - pfy;
        int ix = (int)pfx, iy = (int)pfy;

        unsigned i00, i01, i10, i11;
        if ((lp.hashed_mask >> l) & 1u) {
            unsigned hy0 = (unsigned)iy * 2654435761u;
            unsigned hy1 = (unsigned)(iy + 1) * 2654435761u;
            i00 = ((unsigned)ix       ^ hy0) & (TABLE_SIZE - 1u);
            i01 = ((unsigned)ix       ^ hy1) & (TABLE_SIZE - 1u);
            i10 = ((unsigned)(ix + 1) ^ hy0) & (TABLE_SIZE - 1u);
            i11 = ((unsigned)(ix + 1) ^ hy1) & (TABLE_SIZE - 1u);
        } else {
            int res = lp.res[l];
            i00 = (unsigned)(iy * res + ix);
            i01 = i00 + (unsigned)res;
            i10 = i00 + 1u;
            i11 = i01 + 1u;
        }

        const float4* tab = emb + (size_t)l * TABLE_SIZE;
        float4 c00 = __ldg(tab + i00);
        float4 c01 = __ldg(tab + i01);
        float4 c10 = __ldg(tab + i10);
        float4 c11 = __ldg(tab + i11);

        float w00 = (1.0f - frx) * (1.0f - fry);
        float w01 = (1.0f - frx) * fry;
        float w10 = frx * (1.0f - fry);
        float w11 = frx * fry;

        float f0 = ((c00.x * w00 + c01.x * w01) + c10.x * w10) + c11.x * w11;
        float f1 = ((c00.y * w00 + c01.y * w01) + c10.y * w10) + c11.y * w11;
        float f2 = ((c00.z * w00 + c01.z * w01) + c10.z * w10) + c11.z * w11;
        float f3 = ((c00.w * w00 + c01.w * w01) + c10.w * w10) + c11.w * w11;

        float h0 = __bfloat162float(__float2bfloat16(f0));
        float h1 = __bfloat162float(__float2bfloat16(f1));
        float h2 = __bfloat162float(__float2bfloat16(f2));
        float h3 = __bfloat162float(__float2bfloat16(f3));

        uint4 pk;
        pk.x = pack_bf16x2(h0, h1);
        pk.y = pack_bf16x2(f0 - h0, f1 - h1);
        pk.z = pack_bf16x2(h2, h3);
        pk.w = pack_bf16x2(f2 - h2, f3 - h3);
        *(uint4*)(f_row + l * 2) = pk;
    }

    __syncthreads();

    // ---- Phase 2: 32x32 warp tiles, single pass over K ----
    // Warp w covers rows (w&3)*32, cols (w>>2)*32. A read once, B halved.
    const int warp = tid >> 5;
    const int lane = tid & 31;
    const int r = lane >> 2;
    const int c = lane & 3;
    const int wrow = (warp & 3) * 32;
    const int wcol = (warp >> 2) * 32;          // 0 or 32

    const uint2* Ab = FHL + wrow * FS64;

    float C0[4][4], C1[4][4];
    #pragma unroll
    for (int nt = 0; nt < 4; ++nt) {            // fold b0 into accumulator init
        int col0 = wcol + nt * 8 + 2 * c;
        float ba = sb0[col0], bb = sb0[col0 + 1];
        C0[nt][0] = ba; C0[nt][1] = bb; C0[nt][2] = ba; C0[nt][3] = bb;
        C1[nt][0] = ba; C1[nt][1] = bb; C1[nt][2] = ba; C1[nt][3] = bb;
    }

    #pragma unroll
    for (int kk = 0; kk < 4; ++kk) {
        int kb2 = kk * 8;
        uint2 a00 = Ab[r * FS64 + kb2 + c];            // rowtile 0
        uint2 a01 = Ab[(r + 8) * FS64 + kb2 + c];
        uint2 a02 = Ab[r * FS64 + kb2 + c + 4];
        uint2 a03 = Ab[(r + 8) * FS64 + kb2 + c + 4];
        uint2 a10 = Ab[(r + 16) * FS64 + kb2 + c];     // rowtile 1
        uint2 a11 = Ab[(r + 24) * FS64 + kb2 + c];
        uint2 a12 = Ab[(r + 16) * FS64 + kb2 + c + 4];
        uint2 a13 = Ab[(r + 24) * FS64 + kb2 + c + 4];

        const uint2* B0 = BHL + (kb2 + c) * WS64 + wcol;
        const uint2* B4 = BHL + (kb2 + c + 4) * WS64 + wcol;
        #pragma unroll
        for (int nt = 0; nt < 4; ++nt) {
            int n = nt * 8 + r;
            uint2 bv0 = B0[n];
            uint2 bv1 = B4[n];
            MMA_BF16(C0[nt], a00.x, a01.x, a02.x, a03.x, bv0.x, bv1.x);
            MMA_BF16(C0[nt], a00.x, a01.x, a02.x, a03.x, bv0.y, bv1.y);
            MMA_BF16(C0[nt], a00.y, a01.y, a02.y, a03.y, bv0.x, bv1.x);
            MMA_BF16(C1[nt], a10.x, a11.x, a12.x, a13.x, bv0.x, bv1.x);
            MMA_BF16(C1[nt], a10.x, a11.x, a12.x, a13.x, bv0.y, bv1.y);
            MMA_BF16(C1[nt], a10.y, a11.y, a12.y, a13.y, bv0.x, bv1.x);
        }
    }

    // ---- Epilogue: per-warp partials over its 32 cols, then cross-warp sum ----
    float s00 = 0.f, s01 = 0.f, s10 = 0.f, s11 = 0.f;
    #pragma unroll
    for (int nt = 0; nt < 4; ++nt) {
        int col0 = wcol + nt * 8 + 2 * c;
        float w1a = sW1[col0], w1b = sW1[col0 + 1];
        s00 += softplus10(C0[nt][0]) * w1a;
        s00 += softplus10(C0[nt][1]) * w1b;
        s01 += softplus10(C0[nt][2]) * w1a;
        s01 += softplus10(C0[nt][3]) * w1b;
        s10 += softplus10(C1[nt][0]) * w1a;
        s10 += softplus10(C1[nt][1]) * w1b;
        s11 += softplus10(C1[nt][2]) * w1a;
        s11 += softplus10(C1[nt][3]) * w1b;
    }
    s00 += __shfl_xor_sync(0xffffffffu, s00, 1);
    s00 += __shfl_xor_sync(0xffffffffu, s00, 2);
    s01 += __shfl_xor_sync(0xffffffffu, s01, 1);
    s01 += __shfl_xor_sync(0xffffffffu, s01, 2);
    s10 += __shfl_xor_sync(0xffffffffu, s10, 1);
    s10 += __shfl_xor_sync(0xffffffffu, s10, 2);
    s11 += __shfl_xor_sync(0xffffffffu, s11, 1);
    s11 += __shfl_xor_sync(0xffffffffu, s11, 2);

    // warps 0-3 (cols 0-31): stash partials; warps 4-7 (cols 32-63): finish
    if (warp < 4 && c == 0) {
        sbuf[wrow + r]      = s00;
        sbuf[wrow + r + 8]  = s01;
        sbuf[wrow + r + 16] = s10;
        sbuf[wrow + r + 24] = s11;
    }
    __syncthreads();

    if (warp >= 4 && c == 0) {
        float b1v = sb1[0];
        float sv[4] = { s00, s01, s10, s11 };
        #pragma unroll
        for (int q = 0; q < 4; ++q) {
            int local = wrow + q * 8 + r;
            float sig = sbuf[local] + sv[q];     // cols 0-31 + cols 32-63
            int pp = blockIdx.x * PTS + local;
            int rr = pp / TSAMP;
            int tt = pp - rr * TSAMP;
            float sigma = softplus10(b1v + sig);
            float zt  = step * (float)tt;
            float zt1 = step * (float)(tt - 1);
            float delta = (tt == 0) ? (1.0f / 192.0f) : (zt - zt1);
            out[pp] = delta * sigma;
        }
    }
}

extern "C" void kernel_launch(void* const* d_in, const int* in_sizes, int n_in,
                              void* d_out, int out_size) {
    const float* x   = (const float*)d_in[0];   // [4,2048,192,2]
    const float* emb = (const float*)d_in[1];   // [16, 524288, 4]
    const float* W0  = (const float*)d_in[2];   // [64,64]
    const float* b0  = (const float*)d_in[3];   // [64]
    const float* W1  = (const float*)d_in[4];   // [64,1]
    const float* b1  = (const float*)d_in[5];   // [1]
    float* out = (float*)d_out;

    LevelParams lp;
    const double b = exp((log(2048.0) - log(2.0)) / 15.0);
    unsigned mask = 0;
    for (int l = 0; l < NUM_LEVELS; ++l) {
        double s = 2.0 * pow(b, (double)l) - 1.0;
        lp.scale[l] = (float)s;
        int res = (int)ceil(s) + 1;
        lp.res[l] = res;
        if ((long long)res * (long long)res > (long long)TABLE_SIZE)
            mask |= (1u << l);
    }
    lp.hashed_mask = mask;

    const int smem_bytes = (PTS * FS64 + 32 * WS64) * 8
                         + (64 + 64 + PTS + 4) * 4;
    static int attr_set = 0;
    if (!attr_set) {
        cudaFuncSetAttribute(nerf_fused,
                             cudaFuncAttributeMaxDynamicSharedMemorySize,
                             smem_bytes);
        attr_set = 1;
    }

    int n_points = in_sizes[0] / 2;             // 1,572,864
    int n_blocks = n_points / PTS;              // 12288
    nerf_fused<<<n_blocks, NTHREADS, smem_bytes>>>(x, (const float4*)emb,
                                                   W0, b0, W1, b1, out, lp);
}

// round 15
// speedup vs baseline: 1.6824x; 1.6824x over previous
#include <cuda_runtime.h>
#include <cuda_bf16.h>
#include <math.h>

#define NUM_LEVELS 16
#define TABLE_SIZE (1u << 19)
#define TSAMP 192
#define PTS 128            // points per block
#define NTHREADS 256
#define FS64 36            // feats row stride, uint2(8B) units: (4r+c)%16 bijective
#define WS64 68            // W row stride, uint2 units: (4c+r)%16 bijective

struct LevelParams {
    float scale[NUM_LEVELS];
    int   res[NUM_LEVELS];
    unsigned hashed_mask;
};

__device__ __forceinline__ float softplus10(float v) {
    float y = 10.0f * v;
    float t = __expf(-fabsf(y));
    return (fmaxf(y, 0.0f) + __logf(1.0f + t)) * 0.1f;
}

__device__ __forceinline__ unsigned pack_bf16x2(float lo_val, float hi_val) {
    // lo_val -> low 16 bits (element k), hi_val -> high 16 bits (element k+1)
    unsigned r;
    asm("cvt.rn.bf16x2.f32 %0, %1, %2;" : "=r"(r) : "f"(hi_val), "f"(lo_val));
    return r;
}

#define MMA_BF16(C, A0, A1, A2, A3, B0, B1)                                    \
    asm volatile(                                                              \
        "mma.sync.aligned.m16n8k16.row.col.f32.bf16.bf16.f32 "                 \
        "{%0,%1,%2,%3}, {%4,%5,%6,%7}, {%8,%9}, {%0,%1,%2,%3};"                \
        : "+f"(C[0]), "+f"(C[1]), "+f"(C[2]), "+f"(C[3])                       \
        : "r"(A0), "r"(A1), "r"(A2), "r"(A3), "r"(B0), "r"(B1));

__global__ __launch_bounds__(NTHREADS, 3)
void nerf_fused(const float* __restrict__ x,
                const float4* __restrict__ emb,
                const float* __restrict__ W0,
                const float* __restrict__ b0,
                const float* __restrict__ W1,
                const float* __restrict__ b1,
                float* __restrict__ out,
                LevelParams lp)
{
    extern __shared__ unsigned smu[];
    uint2* FHL = (uint2*)smu;                  // [PTS][FS64]  {hi,lo} bf16x2 feats
    uint2* BHL = FHL + PTS * FS64;             // [32][WS64]   {hi,lo} bf16x2 W0
    float* sb0 = (float*)(BHL + 32 * WS64);    // [64]
    float* sW1 = sb0 + 64;                     // [64]
    float* sb1 = sW1 + 64;                     // [1]

    const int tid = threadIdx.x;

    // ---- W0 -> bf16 {hi,lo}, packed over k-pairs, interleaved ----
    for (int e = tid; e < 2048; e += NTHREADS) {
        int k2 = e >> 6, n = e & 63;
        float w0v = W0[(2 * k2) * 64 + n];
        float w1v = W0[(2 * k2 + 1) * 64 + n];
        float h0f = __bfloat162float(__float2bfloat16(w0v));
        float h1f = __bfloat162float(__float2bfloat16(w1v));
        uint2 v;
        v.x = pack_bf16x2(h0f, h1f);
        v.y = pack_bf16x2(w0v - h0f, w1v - h1f);
        BHL[k2 * WS64 + n] = v;
    }
    if (tid < 64) { sb0[tid] = b0[tid]; sW1[tid] = W1[tid]; }
    if (tid == 0) { sb1[0] = b1[0]; }

    // ---- Phase 1: gather; 2 threads/point, interleaved levels,
    //      software-pipelined depth 2 (level l+1 loads issued before interp l)
    const int pt   = tid & (PTS - 1);
    const int half = tid >> 7;
    const int p    = blockIdx.x * PTS + pt;
    const int ray  = p / TSAMP;
    const int t    = p - ray * TSAMP;

    const float2* xr = (const float2*)(x + (size_t)ray * (TSAMP * 2));
    float2 o  = xr[0];
    float2 en = xr[TSAMP - 1];
    float dxr = en.x - o.x, dyr = en.y - o.y;
    float nrm = sqrtf(dxr * dxr + dyr * dyr);
    dxr /= nrm; dyr /= nrm;

    const float step = 2.0f / 191.0f;
    float z  = step * (float)t;
    float ux = (fminf(fmaxf(o.x + dxr * z, -1.0f), 1.0f) + 1.0f) * 0.5f;
    float uy = (fminf(fmaxf(o.y + dyr * z, -1.0f), 1.0f) + 1.0f) * 0.5f;

    uint2* f_row = FHL + pt * FS64;

    // double-buffered level state
    unsigned pidx[2][4];
    float    pfrx[2], pfry[2];
    const float4* ptab[2];
    float4 ld[2][4];

    // --- prologue: compute + issue loads for level slot l2=0 ---
    {
        int l = half;                            // 2*0 + half
        float s = lp.scale[l];
        float posx = ux * s + 0.5f;
        float posy = uy * s + 0.5f;
        float pfx = floorf(posx), pfy = floorf(posy);
        pfrx[0] = posx - pfx; pfry[0] = posy - pfy;
        int ix = (int)pfx, iy = (int)pfy;
        if ((lp.hashed_mask >> l) & 1u) {
            unsigned hy0 = (unsigned)iy * 2654435761u;
            unsigned hy1 = (unsigned)(iy + 1) * 2654435761u;
            pidx[0][0] = ((unsigned)ix       ^ hy0) & (TABLE_SIZE - 1u);
            pidx[0][1] = ((unsigned)ix       ^ hy1) & (TABLE_SIZE - 1u);
            pidx[0][2] = ((unsigned)(ix + 1) ^ hy0) & (TABLE_SIZE - 1u);
            pidx[0][3] = ((unsigned)(ix + 1) ^ hy1) & (TABLE_SIZE - 1u);
        } else {
            int res = lp.res[l];
            unsigned i00 = (unsigned)(iy * res + ix);
            pidx[0][0] = i00;
            pidx[0][1] = i00 + (unsigned)res;
            pidx[0][2] = i00 + 1u;
            pidx[0][3] = i00 + (unsigned)res + 1u;
        }
        ptab[0] = emb + (size_t)l * TABLE_SIZE;
        ld[0][0] = __ldg(ptab[0] + pidx[0][0]);
        ld[0][1] = __ldg(ptab[0] + pidx[0][1]);
        ld[0][2] = __ldg(ptab[0] + pidx[0][2]);
        ld[0][3] = __ldg(ptab[0] + pidx[0][3]);
    }

    #pragma unroll
    for (int l2 = 0; l2 < 8; ++l2) {
        const int cur = l2 & 1;
        const int nxt = cur ^ 1;

        // compute + issue loads for level l2+1 BEFORE consuming level l2
        if (l2 < 7) {
            int ln = 2 * (l2 + 1) + half;
            float s = lp.scale[ln];
            float posx = ux * s + 0.5f;
            float posy = uy * s + 0.5f;
            float pfx = floorf(posx), pfy = floorf(posy);
            pfrx[nxt] = posx - pfx; pfry[nxt] = posy - pfy;
            int ix = (int)pfx, iy = (int)pfy;
            if ((lp.hashed_mask >> ln) & 1u) {
                unsigned hy0 = (unsigned)iy * 2654435761u;
                unsigned hy1 = (unsigned)(iy + 1) * 2654435761u;
                pidx[nxt][0] = ((unsigned)ix       ^ hy0) & (TABLE_SIZE - 1u);
                pidx[nxt][1] = ((unsigned)ix       ^ hy1) & (TABLE_SIZE - 1u);
                pidx[nxt][2] = ((unsigned)(ix + 1) ^ hy0) & (TABLE_SIZE - 1u);
                pidx[nxt][3] = ((unsigned)(ix + 1) ^ hy1) & (TABLE_SIZE - 1u);
            } else {
                int res = lp.res[ln];
                unsigned i00 = (unsigned)(iy * res + ix);
                pidx[nxt][0] = i00;
                pidx[nxt][1] = i00 + (unsigned)res;
                pidx[nxt][2] = i00 + 1u;
                pidx[nxt][3] = i00 + (unsigned)res + 1u;
            }
            ptab[nxt] = emb + (size_t)ln * TABLE_SIZE;
            ld[nxt][0] = __ldg(ptab[nxt] + pidx[nxt][0]);
            ld[nxt][1] = __ldg(ptab[nxt] + pidx[nxt][1]);
            ld[nxt][2] = __ldg(ptab[nxt] + pidx[nxt][2]);
            ld[nxt][3] = __ldg(ptab[nxt] + pidx[nxt][3]);
        }

        // consume level l2
        int l = 2 * l2 + half;
        float frx = pfrx[cur], fry = pfry[cur];
        float w00 = (1.0f - frx) * (1.0f - fry);
        float w01 = (1.0f - frx) * fry;
        float w10 = frx * (1.0f - fry);
        float w11 = frx * fry;

        float4 c00 = ld[cur][0], c01 = ld[cur][1];
        float4 c10 = ld[cur][2], c11 = ld[cur][3];

        float f0 = ((c00.x * w00 + c01.x * w01) + c10.x * w10) + c11.x * w11;
        float f1 = ((c00.y * w00 + c01.y * w01) + c10.y * w10) + c11.y * w11;
        float f2 = ((c00.z * w00 + c01.z * w01) + c10.z * w10) + c11.z * w11;
        float f3 = ((c00.w * w00 + c01.w * w01) + c10.w * w10) + c11.w * w11;

        float h0 = __bfloat162float(__float2bfloat16(f0));
        float h1 = __bfloat162float(__float2bfloat16(f1));
        float h2 = __bfloat162float(__float2bfloat16(f2));
        float h3 = __bfloat162float(__float2bfloat16(f3));

        uint4 pk;
        pk.x = pack_bf16x2(h0, h1);
        pk.y = pack_bf16x2(f0 - h0, f1 - h1);
        pk.z = pack_bf16x2(h2, h3);
        pk.w = pack_bf16x2(f2 - h2, f3 - h3);
        *(uint4*)(f_row + l * 2) = pk;
    }

    __syncthreads();

    // ---- Phase 2: per-warp m16n8k16 bf16 GEMM, 3-pass split, LDS.64 ----
    // Two sequential 32-column halves: C stays 4x4 -> low reg pressure.
    const int warp = tid >> 5;
    const int lane = tid & 31;
    const int r = lane >> 2;
    const int c = lane & 3;

    const uint2* Ab = FHL + (warp * 16) * FS64;
    float sig0 = 0.f, sig1 = 0.f;

    #pragma unroll
    for (int ch = 0; ch < 2; ++ch) {
        float C[4][4];
        #pragma unroll
        for (int nt = 0; nt < 4; ++nt) {        // fold b0 into accumulator init
            int col0 = ch * 32 + nt * 8 + 2 * c;
            float ba = sb0[col0], bb = sb0[col0 + 1];
            C[nt][0] = ba; C[nt][1] = bb; C[nt][2] = ba; C[nt][3] = bb;
        }

        #pragma unroll
        for (int kk = 0; kk < 4; ++kk) {
            int kb2 = kk * 8;
            uint2 a0 = Ab[r * FS64 + kb2 + c];         // .x = hi, .y = lo
            uint2 a1 = Ab[(r + 8) * FS64 + kb2 + c];
            uint2 a2 = Ab[r * FS64 + kb2 + c + 4];
            uint2 a3 = Ab[(r + 8) * FS64 + kb2 + c + 4];

            const uint2* B0 = BHL + (kb2 + c) * WS64 + ch * 32;
            const uint2* B4 = BHL + (kb2 + c + 4) * WS64 + ch * 32;
            #pragma unroll
            for (int nt = 0; nt < 4; ++nt) {
                int n = nt * 8 + r;
                uint2 bv0 = B0[n];
                uint2 bv1 = B4[n];
                MMA_BF16(C[nt], a0.x, a1.x, a2.x, a3.x, bv0.x, bv1.x);
                MMA_BF16(C[nt], a0.x, a1.x, a2.x, a3.x, bv0.y, bv1.y);
                MMA_BF16(C[nt], a0.y, a1.y, a2.y, a3.y, bv0.x, bv1.x);
            }
        }

        // partial epilogue for this column half
        #pragma unroll
        for (int nt = 0; nt < 4; ++nt) {
            int col0 = ch * 32 + nt * 8 + 2 * c;
            float w1a = sW1[col0], w1b = sW1[col0 + 1];
            sig0 += softplus10(C[nt][0]) * w1a;
            sig0 += softplus10(C[nt][1]) * w1b;
            sig1 += softplus10(C[nt][2]) * w1a;
            sig1 += softplus10(C[nt][3]) * w1b;
        }
    }

    sig0 += __shfl_xor_sync(0xffffffffu, sig0, 1);
    sig0 += __shfl_xor_sync(0xffffffffu, sig0, 2);
    sig1 += __shfl_xor_sync(0xffffffffu, sig1, 1);
    sig1 += __shfl_xor_sync(0xffffffffu, sig1, 2);

    if (c == 0) {
        float b1v = sb1[0];
        #pragma unroll
        for (int hrow = 0; hrow < 2; ++hrow) {
            int local = warp * 16 + r + hrow * 8;
            int pp = blockIdx.x * PTS + local;
            int rr = pp / TSAMP;
            int tt = pp - rr * TSAMP;
            float sigv  = (hrow == 0) ? sig0 : sig1;
            float sigma = softplus10(b1v + sigv);
            float zt  = step * (float)tt;
            float zt1 = step * (float)(tt - 1);
            float delta = (tt == 0) ? (1.0f / 192.0f) : (zt - zt1);
            out[pp] = delta * sigma;
        }
    }
}

extern "C" void kernel_launch(void* const* d_in, const int* in_sizes, int n_in,
                              void* d_out, int out_size) {
    const float* x   = (const float*)d_in[0];   // [4,2048,192,2]
    const float* emb = (const float*)d_in[1];   // [16, 524288, 4]
    const float* W0  = (const float*)d_in[2];   // [64,64]
    const float* b0  = (const float*)d_in[3];   // [64]
    const float* W1  = (const float*)d_in[4];   // [64,1]
    const float* b1  = (const float*)d_in[5];   // [1]
    float* out = (float*)d_out;

    LevelParams lp;
    const double b = exp((log(2048.0) - log(2.0)) / 15.0);
    unsigned mask = 0;
    for (int l = 0; l < NUM_LEVELS; ++l) {
        double s = 2.0 * pow(b, (double)l) - 1.0;
        lp.scale[l] = (float)s;
        int res = (int)ceil(s) + 1;
        lp.res[l] = res;
        if ((long long)res * (long long)res > (long long)TABLE_SIZE)
            mask |= (1u << l);
    }
    lp.hashed_mask = mask;

    const int smem_bytes = (PTS * FS64 + 32 * WS64) * 8 + (64 + 64 + 4) * 4;
    static int attr_set = 0;
    if (!attr_set) {
        cudaFuncSetAttribute(nerf_fused,
                             cudaFuncAttributeMaxDynamicSharedMemorySize,
                             smem_bytes);
        attr_set = 1;
    }

    int n_points = in_sizes[0] / 2;             // 1,572,864
    int n_blocks = n_points / PTS;              // 12288
    nerf_fused<<<n_blocks, NTHREADS, smem_bytes>>>(x, (const float4*)emb,
                                                   W0, b0, W1, b1, out, lp);
}